// round 1
// baseline (speedup 1.0000x reference)
#include <cuda_runtime.h>
#include <math.h>

// Problem shape (fixed by the reference setup_inputs):
//   template:    (5, 8, 2)  float32
//   projections: (5000, 8, 2) float32
// Output: concat( w_sel (5000,5,8,3) f32 , indices (5000,5,8,3) -> float )
static constexpr int V  = 5000;
static constexpr int R  = 5;
static constexpr int A  = 8;
static constexpr int NP = 8;   // points per projection row
static constexpr int K  = 7;   // neighbors (NP - 1)
static constexpr int NT = V * R * A;  // 200000 tasks

__global__ __launch_bounds__(128)
void bc_kernel(const float* __restrict__ tmpl,
               const float* __restrict__ proj,
               float* __restrict__ out)
{
    int task = blockIdx.x * blockDim.x + threadIdx.x;
    if (task >= NT) return;

    int v  = task / (R * A);
    int ra = task - v * (R * A);

    // Template point for this (r, a)
    float tx = tmpl[2 * ra + 0];
    float ty = tmpl[2 * ra + 1];

    // Load this projection row: 8 x 2 floats, vectorized (64B-aligned per row)
    float px[NP], py[NP], key[NP];
    int   id[NP];
    const float4* p4 = reinterpret_cast<const float4*>(proj + v * NP * 2);
    {
        float4 q;
        q = p4[0]; px[0] = q.x; py[0] = q.y; px[1] = q.z; py[1] = q.w;
        q = p4[1]; px[2] = q.x; py[2] = q.y; px[3] = q.z; py[3] = q.w;
        q = p4[2]; px[4] = q.x; py[4] = q.y; px[5] = q.z; py[5] = q.w;
        q = p4[3]; px[6] = q.x; py[6] = q.y; px[7] = q.z; py[7] = q.w;
    }

    // Distance keys (sqrt to match jnp.linalg.norm ordering exactly)
    #pragma unroll
    for (int k = 0; k < NP; k++) {
        float dx = tx - px[k];
        float dy = ty - py[k];
        key[k] = sqrtf(dx * dx + dy * dy);
        id[k]  = k;
    }

    // Stable-equivalent sorting network (Batcher odd-even mergesort, 19 CEs).
    // Tie-break on original index reproduces jnp.argsort's stable order.
    #define CEX(a, b)                                                          \
    {                                                                          \
        bool sw = (key[a] > key[b]) ||                                         \
                  ((key[a] == key[b]) && (id[a] > id[b]));                     \
        float tk = key[a], tpx = px[a], tpy = py[a]; int ti = id[a];           \
        if (sw) {                                                              \
            key[a] = key[b]; px[a] = px[b]; py[a] = py[b]; id[a] = id[b];      \
            key[b] = tk;     px[b] = tpx;  py[b] = tpy;   id[b] = ti;          \
        }                                                                      \
    }
    CEX(0,1) CEX(2,3) CEX(4,5) CEX(6,7)
    CEX(0,2) CEX(1,3) CEX(4,6) CEX(5,7)
    CEX(1,2) CEX(5,6)
    CEX(0,4) CEX(1,5) CEX(2,6) CEX(3,7)
    CEX(2,4) CEX(3,5)
    CEX(1,2) CEX(3,4) CEX(5,6)
    #undef CEX

    // closest = sorted[0]; other[n] = sorted[n+1]
    float cx = px[0], cy = py[0];
    float sc = cx * cx + cy * cy;
    float ox[K], oy[K], so[K], v0x[K], v0y[K], d00[K], d02[K];
    float v2x = tx - cx, v2y = ty - cy;
    #pragma unroll
    for (int n = 0; n < K; n++) {
        ox[n]  = px[n + 1];
        oy[n]  = py[n + 1];
        so[n]  = ox[n] * ox[n] + oy[n] * oy[n];
        v0x[n] = ox[n] - cx;
        v0y[n] = oy[n] - cy;
        d00[n] = v0x[n] * v0x[n] + v0y[n] * v0y[n];
        d02[n] = v0x[n] * v2x + v0y[n] * v2y;
    }

    const float INF = __int_as_float(0x7f800000);
    float best = INF;
    float bw0 = 0.f, bw1 = 0.f, bw2 = 0.f;
    int   bn1 = id[1], bn2 = id[1];   // argmin-of-all-inf default: (row,col)=(0,0)

    #pragma unroll
    for (int i = 0; i < K; i++) {
        #pragma unroll
        for (int j = 0; j < K; j++) {
            if (i == j) continue;
            float d01   = v0x[i] * v0x[j] + v0y[i] * v0y[j];
            float denom = d00[i] * d00[j] - d01 * d01;
            float inv   = 1.0f / denom;
            float w2 = (d00[j] * d02[i] - d01 * d02[j]) * inv;
            float w1 = (d00[i] * d02[j] - d01 * d02[i]) * inv;
            float w0 = 1.0f - w2 - w1;
            // valid iff all strictly positive (NaN compares false -> invalid)
            if (w0 > 0.f && w1 > 0.f && w2 > 0.f) {
                float s = fmaxf(w0 * w0, fmaxf(w1 * w1, w2 * w2));
                if (s < best) {   // strict <  == first-occurrence argmin
                    // In-circle validity: every other neighbor k must give det<=0
                    bool ok = true;
                    #pragma unroll
                    for (int k = 0; k < K; k++) {
                        if (k == i || k == j) continue;
                        float ax = cx - ox[k], ay = cy - oy[k], az = sc - so[k];
                        float bx = ox[i] - ox[k], by = oy[i] - oy[k], bs = so[i] - so[k];
                        float dx = ox[j] - ox[k], dy = oy[j] - oy[k], ds = so[j] - so[k];
                        float det = ax * (by * ds - bs * dy)
                                  - ay * (bx * ds - bs * dx)
                                  + az * (bx * dy - by * dx);
                        ok = ok && (det <= 0.f);   // NaN det -> invalid, matches ref
                    }
                    if (ok) {
                        best = s;
                        bw0 = w0; bw1 = w1; bw2 = w2;
                        bn1 = id[i + 1];
                        bn2 = id[j + 1];
                    }
                }
            }
        }
    }

    // w_sel: stacked order is [w0, w2, w1]; zero if selected weights were inf
    float o0, o1, o2;
    if (best < INF) { o0 = bw0; o1 = bw2; o2 = bw1; }
    else            { o0 = 0.f; o1 = 0.f; o2 = 0.f; }

    out[3 * task + 0] = o0;
    out[3 * task + 1] = o1;
    out[3 * task + 2] = o2;

    float* io = out + 3 * NT;   // indices block (cast to float)
    io[3 * task + 0] = (float)id[0];
    io[3 * task + 1] = (float)bn1;
    io[3 * task + 2] = (float)bn2;
}

extern "C" void kernel_launch(void* const* d_in, const int* in_sizes, int n_in,
                              void* d_out, int out_size)
{
    const float* tmpl = (const float*)d_in[0];
    const float* proj = (const float*)d_in[1];
    float* out = (float*)d_out;

    const int threads = 128;
    const int blocks  = (NT + threads - 1) / threads;
    bc_kernel<<<blocks, threads>>>(tmpl, proj, out);
}

// round 3
// speedup vs baseline: 3.2220x; 3.2220x over previous
#include <cuda_runtime.h>

// Problem shape (fixed by the reference setup_inputs):
//   template:    (5, 8, 2)  float32
//   projections: (5000, 8, 2) float32
// Output: concat( w_sel (5000,5,8,3) f32 , indices (5000,5,8,3) -> float )
static constexpr int V  = 5000;
static constexpr int R  = 5;
static constexpr int A  = 8;
static constexpr int NP = 8;
static constexpr int K  = 7;
static constexpr int NT = V * R * A;  // 200000 tasks

__global__ __launch_bounds__(128, 8)
void bc_kernel(const float* __restrict__ tmpl,
               const float* __restrict__ proj,
               float* __restrict__ out)
{
    int task = blockIdx.x * blockDim.x + threadIdx.x;
    if (task >= NT) return;

    int v  = task / (R * A);
    int ra = task - v * (R * A);

    float tx = tmpl[2 * ra + 0];
    float ty = tmpl[2 * ra + 1];

    // Load projection row (8 points, vectorized)
    float px[NP], py[NP];
    unsigned key[NP];
    const float4* p4 = reinterpret_cast<const float4*>(proj + v * NP * 2);
    {
        float4 q;
        q = p4[0]; px[0] = q.x; py[0] = q.y; px[1] = q.z; py[1] = q.w;
        q = p4[1]; px[2] = q.x; py[2] = q.y; px[3] = q.z; py[3] = q.w;
        q = p4[2]; px[4] = q.x; py[4] = q.y; px[5] = q.z; py[5] = q.w;
        q = p4[3]; px[6] = q.x; py[6] = q.y; px[7] = q.z; py[7] = q.w;
    }

    // Sort keys: squared distance (same order as norm), original index packed
    // into the 3 LSBs (stable tie-break identical to jnp.argsort where ties
    // are genuine). Positive floats compare correctly as unsigned ints.
    #pragma unroll
    for (int k = 0; k < NP; k++) {
        float dx = tx - px[k];
        float dy = ty - py[k];
        float sq = fmaf(dx, dx, dy * dy);
        key[k] = (__float_as_uint(sq) & ~7u) | (unsigned)k;
    }

    // Batcher odd-even mergesort, 19 compare-exchanges, fully predicated.
    #define CEX(a, b)                                                         \
    {                                                                         \
        bool sw = key[a] > key[b];                                            \
        unsigned ku = sw ? key[b] : key[a], kv = sw ? key[a] : key[b];        \
        float    xu = sw ? px[b]  : px[a],  xv = sw ? px[a]  : px[b];         \
        float    yu = sw ? py[b]  : py[a],  yv = sw ? py[a]  : py[b];         \
        key[a] = ku; key[b] = kv; px[a] = xu; px[b] = xv; py[a] = yu; py[b] = yv; \
    }
    CEX(0,1) CEX(2,3) CEX(4,5) CEX(6,7)
    CEX(0,2) CEX(1,3) CEX(4,6) CEX(5,7)
    CEX(1,2) CEX(5,6)
    CEX(0,4) CEX(1,5) CEX(2,6) CEX(3,7)
    CEX(2,4) CEX(3,5)
    CEX(1,2) CEX(3,4) CEX(5,6)
    #undef CEX

    int id0 = (int)(key[0] & 7u);

    // q_m = lifted neighbor-minus-closest vectors (x, y, |p|^2 - |c|^2).
    // Reference det(i,j,k) == -[q_i, q_j, q_k]  (triple product).
    float cx = px[0], cy = py[0];
    float sc = fmaf(cx, cx, cy * cy);
    float v2x = tx - cx, v2y = ty - cy;

    float qx[K], qy[K], qs[K], d00[K], d02[K];
    unsigned idpack = 0;  // 3 bits per neighbor id
    #pragma unroll
    for (int n = 0; n < K; n++) {
        float ox = px[n + 1], oy = py[n + 1];
        qx[n] = ox - cx;
        qy[n] = oy - cy;
        float so = fmaf(ox, ox, oy * oy);
        qs[n] = so - sc;
        d00[n] = fmaf(qx[n], qx[n], qy[n] * qy[n]);
        d02[n] = fmaf(qx[n], v2x, qy[n] * v2y);
        idpack |= (key[n + 1] & 7u) << (3 * n);
    }

    const float INF = __int_as_float(0x7f800000);
    float best = INF;
    float b0 = 0.f, b1 = 0.f, b2 = 0.f;
    int bij = 0;  // (row<<3)|col of selected pair; default (0,0) matches ref argmin-of-inf

    // Per UNORDERED pair: weights/score identical for (i,j) and (j,i)
    // (w2(i,j)==w1(j,i)); incircle dets are exact negations, so one cross
    // product + 5 dots + min/max covers both ordered candidates.
    #pragma unroll
    for (int i = 0; i < K; i++) {
        #pragma unroll
        for (int j = i + 1; j < K; j++) {
            float d01   = fmaf(qx[i], qx[j], qy[i] * qy[j]);
            float denom = fmaf(d00[i], d00[j], -d01 * d01);
            float inv   = __fdividef(1.0f, denom);
            float nA = fmaf(d00[j], d02[i], -d01 * d02[j]);  // w2 of (i,j)
            float nB = fmaf(d00[i], d02[j], -d01 * d02[i]);  // w1 of (i,j)
            float w2 = nA * inv;
            float w1 = nB * inv;
            float w0 = 1.0f - w2 - w1;
            bool wpos = (w0 > 0.f) && (w1 > 0.f) && (w2 > 0.f);
            float s = fmaxf(w0 * w0, fmaxf(w1 * w1, w2 * w2));

            // cross = q_i x q_j ; m_k = cross . q_k = [q_i,q_j,q_k]
            float crx = fmaf(qy[i], qs[j], -qs[i] * qy[j]);
            float cry = fmaf(qs[i], qx[j], -qx[i] * qs[j]);
            float crz = fmaf(qx[i], qy[j], -qy[i] * qx[j]);
            float mn = INF, mx = -INF;
            #pragma unroll
            for (int k = 0; k < K; k++) {
                if (k == i || k == j) continue;
                float m = fmaf(crx, qx[k], fmaf(cry, qy[k], crz * qs[k]));
                mn = fminf(mn, m);
                mx = fmaxf(mx, m);
            }
            // (i,j): det<=0 forall k  <=>  m>=0 forall k
            bool c1 = wpos && (mn >= 0.f);
            bool c2 = wpos && (mx <= 0.f);
            float scand = (c1 || c2) ? s : INF;
            if (scand < best) {  // strict < == row-major first occurrence
                best = scand;
                b0 = w0;
                b1 = c1 ? w2 : w1;   // output slot 1 = w2 of selected order
                b2 = c1 ? w1 : w2;   // output slot 2 = w1 of selected order
                bij = c1 ? ((i << 3) | j) : ((j << 3) | i);
            }
        }
    }

    bool has = best < INF;
    int row = bij >> 3, col = bij & 7;
    int bn1 = (int)((idpack >> (3 * row)) & 7u);
    int bn2 = (int)((idpack >> (3 * col)) & 7u);

    out[3 * task + 0] = has ? b0 : 0.f;
    out[3 * task + 1] = has ? b1 : 0.f;
    out[3 * task + 2] = has ? b2 : 0.f;

    float* io = out + 3 * NT;
    io[3 * task + 0] = (float)id0;
    io[3 * task + 1] = (float)bn1;
    io[3 * task + 2] = (float)bn2;
}

extern "C" void kernel_launch(void* const* d_in, const int* in_sizes, int n_in,
                              void* d_out, int out_size)
{
    const float* tmpl = (const float*)d_in[0];
    const float* proj = (const float*)d_in[1];
    float* out = (float*)d_out;

    const int threads = 128;
    const int blocks  = (NT + threads - 1) / threads;
    bc_kernel<<<blocks, threads>>>(tmpl, proj, out);
}

// round 7
// speedup vs baseline: 3.5301x; 1.0956x over previous
#include <cuda_runtime.h>

// Problem shape (fixed by the reference setup_inputs):
//   template:    (5, 8, 2)  float32
//   projections: (5000, 8, 2) float32
// Output: concat( w_sel (5000,5,8,3) f32 , indices (5000,5,8,3) -> float )
static constexpr int V  = 5000;
static constexpr int R  = 5;
static constexpr int A  = 8;
static constexpr int NP = 8;
static constexpr int K  = 7;
static constexpr int NT = V * R * A;  // 200000 tasks

__global__ __launch_bounds__(128, 8)
void bc_kernel(const float* __restrict__ tmpl,
               const float* __restrict__ proj,
               float* __restrict__ out)
{
    int task = blockIdx.x * blockDim.x + threadIdx.x;
    if (task >= NT) return;

    int v  = task / (R * A);
    int ra = task - v * (R * A);

    float tx = tmpl[2 * ra + 0];
    float ty = tmpl[2 * ra + 1];

    // Load projection row (8 points, vectorized)
    float px[NP], py[NP];
    const float4* p4 = reinterpret_cast<const float4*>(proj + v * NP * 2);
    {
        float4 q;
        q = p4[0]; px[0] = q.x; py[0] = q.y; px[1] = q.z; py[1] = q.w;
        q = p4[1]; px[2] = q.x; py[2] = q.y; px[3] = q.z; py[3] = q.w;
        q = p4[2]; px[4] = q.x; py[4] = q.y; px[5] = q.z; py[5] = q.w;
        q = p4[3]; px[6] = q.x; py[6] = q.y; px[7] = q.z; py[7] = q.w;
    }

    // Packed keys: squared distance bits (order == norm order for non-negative
    // floats compared as unsigned) with the original index in the 3 LSBs so
    // min() reproduces jnp.argsort's stable tie-break.
    unsigned key[NP];
    #pragma unroll
    for (int k = 0; k < NP; k++) {
        float dx = tx - px[k];
        float dy = ty - py[k];
        float sq = fmaf(dx, dx, dy * dy);
        key[k] = (__float_as_uint(sq) & ~7u) | (unsigned)k;
    }

    // min1/min2 tournament (closest + second-closest). No full sort needed:
    // the winning pair / orientation / ids are invariant to the order of the
    // non-closest points; only closest (always) and second-closest (ref's
    // default when no candidate is valid) depend on order.
    unsigned m1, m2;
    {
        unsigned a1 = umin(key[0], key[1]), a2 = umax(key[0], key[1]);
        unsigned b1 = umin(key[2], key[3]), b2 = umax(key[2], key[3]);
        unsigned c1_ = umin(key[4], key[5]), c2_ = umax(key[4], key[5]);
        unsigned d1 = umin(key[6], key[7]), d2 = umax(key[6], key[7]);
        unsigned e1 = umin(a1, b1);
        unsigned e2 = umin(umax(a1, b1), umin(a2, b2));
        unsigned f1 = umin(c1_, d1);
        unsigned f2 = umin(umax(c1_, d1), umin(c2_, d2));
        m1 = umin(e1, f1);
        m2 = umin(umax(e1, f1), umin(e2, f2));
    }
    int id0 = (int)(m1 & 7u);
    int id1 = (int)(m2 & 7u);

    // Extract closest point via 3-level mux on id0 bits
    float cx, cy;
    {
        bool s0 = (id0 & 1), s1 = (id0 & 2), s2 = (id0 & 4);
        float x01 = s0 ? px[1] : px[0], x23 = s0 ? px[3] : px[2];
        float x45 = s0 ? px[5] : px[4], x67 = s0 ? px[7] : px[6];
        float y01 = s0 ? py[1] : py[0], y23 = s0 ? py[3] : py[2];
        float y45 = s0 ? py[5] : py[4], y67 = s0 ? py[7] : py[6];
        float x03 = s1 ? x23 : x01, x47 = s1 ? x67 : x45;
        float y03 = s1 ? y23 : y01, y47 = s1 ? y67 : y45;
        cx = s2 ? x47 : x03;
        cy = s2 ? y47 : y03;
    }

    // Compact the 7 others in ORIGINAL index order (slot n -> original id
    // n + (n >= id0)), and lift: q_m = (o-c, |o|^2-|c|^2).
    // Reference det(i,j,k) == -[q_i, q_j, q_k] (triple product).
    float sc  = fmaf(cx, cx, cy * cy);
    float v2x = tx - cx, v2y = ty - cy;

    float qx[K], qy[K], qs[K], d00[K], d02[K];
    #pragma unroll
    for (int n = 0; n < K; n++) {
        bool ge = (n >= id0);
        float ox = ge ? px[n + 1] : px[n];
        float oy = ge ? py[n + 1] : py[n];
        qx[n]  = ox - cx;
        qy[n]  = oy - cy;
        qs[n]  = fmaf(ox, ox, oy * oy) - sc;
        d00[n] = fmaf(qx[n], qx[n], qy[n] * qy[n]);
        d02[n] = fmaf(qx[n], v2x, qy[n] * v2y);
    }

    const float INF = __int_as_float(0x7f800000);
    float best = INF;
    float wAs = 0.f, wBs = 0.f;
    int code = 0;

    // Per UNORDERED pair: weights/score identical for both orders
    // (w2(i,j)==w1(j,i)); incircle dets are exact negations, so one cross
    // product + dots + min/max covers both ordered candidates.
    #pragma unroll
    for (int i = 0; i < K; i++) {
        #pragma unroll
        for (int j = i + 1; j < K; j++) {
            float d01   = fmaf(qx[i], qx[j], qy[i] * qy[j]);
            float denom = fmaf(d00[i], d00[j], -d01 * d01);
            float inv   = __fdividef(1.0f, denom);
            float nA = fmaf(d00[j], d02[i], -d01 * d02[j]);  // -> w2 of (i,j)
            float nB = fmaf(d00[i], d02[j], -d01 * d02[i]);  // -> w1 of (i,j)
            float wA = nA * inv;
            float wB = nB * inv;
            float w0 = 1.0f - wA - wB;
            bool wpos = (w0 > 0.f) && (wA > 0.f) && (wB > 0.f);  // NaN -> false
            float s = fmaxf(w0 * w0, fmaxf(wA * wA, wB * wB));

            // cross = q_i x q_j ; m_k = [q_i,q_j,q_k]
            float crx = fmaf(qy[i], qs[j], -qs[i] * qy[j]);
            float cry = fmaf(qs[i], qx[j], -qx[i] * qs[j]);
            float crz = fmaf(qx[i], qy[j], -qy[i] * qx[j]);
            float mn, mx;
            bool first = true;
            #pragma unroll
            for (int k = 0; k < K; k++) {
                if (k == i || k == j) continue;
                float m = fmaf(crx, qx[k], fmaf(cry, qy[k], crz * qs[k]));
                if (first) { mn = m; mx = m; first = false; }
                else       { mn = fminf(mn, m); mx = fmaxf(mx, m); }
            }
            // (i,j) valid <=> det<=0 forall k <=> m_k>=0 forall k
            bool c1 = wpos && (mn >= 0.f);
            bool c2 = wpos && (mx <= 0.f);
            // s is non-NaN whenever (c1|c2); strict < == first-occurrence argmin
            if ((c1 || c2) && (s < best)) {
                best = s;
                wAs  = wA;
                wBs  = wB;
                code = c1 ? ((i << 3) | j) : ((j << 3) | i);
            }
        }
    }

    bool has = best < INF;
    int row = code >> 3, col = code & 7;
    bool fwd = row < col;          // true <=> orientation c1 was selected
    float b0 = 1.0f - wAs - wBs;
    float b1 = fwd ? wAs : wBs;    // w2 of selected ordered pair
    float b2 = fwd ? wBs : wAs;    // w1 of selected ordered pair

    int bn1 = has ? (row + (row >= id0 ? 1 : 0)) : id1;
    int bn2 = has ? (col + (col >= id0 ? 1 : 0)) : id1;

    out[3 * task + 0] = has ? b0 : 0.f;
    out[3 * task + 1] = has ? b1 : 0.f;
    out[3 * task + 2] = has ? b2 : 0.f;

    float* io = out + 3 * NT;
    io[3 * task + 0] = (float)id0;
    io[3 * task + 1] = (float)bn1;
    io[3 * task + 2] = (float)bn2;
}

extern "C" void kernel_launch(void* const* d_in, const int* in_sizes, int n_in,
                              void* d_out, int out_size)
{
    const float* tmpl = (const float*)d_in[0];
    const float* proj = (const float*)d_in[1];
    float* out = (float*)d_out;

    const int threads = 128;
    const int blocks  = (NT + threads - 1) / threads;
    bc_kernel<<<blocks, threads>>>(tmpl, proj, out);
}

// round 12
// speedup vs baseline: 3.6595x; 1.0366x over previous
#include <cuda_runtime.h>

// Problem shape (fixed by the reference setup_inputs):
//   template:    (5, 8, 2)  float32
//   projections: (5000, 8, 2) float32
// Output: concat( w_sel (5000,5,8,3) f32 , indices (5000,5,8,3) -> float )
static constexpr int V  = 5000;
static constexpr int R  = 5;
static constexpr int A  = 8;
static constexpr int NP = 8;
static constexpr int K  = 7;
static constexpr int NT = V * R * A;  // 200000 tasks

// Rank of combination (a<b<c) drawn from {0..6}; 35 total.
__host__ __device__ constexpr int tidx(int a, int b, int c) {
    int r = 0;
    for (int x = 0; x < a; x++) r += (6 - x) * (5 - x) / 2;
    for (int y = a + 1; y < b; y++) r += (6 - y);
    r += c - b - 1;
    return r;
}

__global__ __launch_bounds__(128, 6)
void bc_kernel(const float* __restrict__ tmpl,
               const float* __restrict__ proj,
               float* __restrict__ out)
{
    int task = blockIdx.x * blockDim.x + threadIdx.x;
    if (task >= NT) return;

    int v  = task / (R * A);
    int ra = task - v * (R * A);

    float tx = tmpl[2 * ra + 0];
    float ty = tmpl[2 * ra + 1];

    // Load projection row (8 points, vectorized)
    float px[NP], py[NP];
    const float4* p4 = reinterpret_cast<const float4*>(proj + v * NP * 2);
    {
        float4 q;
        q = p4[0]; px[0] = q.x; py[0] = q.y; px[1] = q.z; py[1] = q.w;
        q = p4[1]; px[2] = q.x; py[2] = q.y; px[3] = q.z; py[3] = q.w;
        q = p4[2]; px[4] = q.x; py[4] = q.y; px[5] = q.z; py[5] = q.w;
        q = p4[3]; px[6] = q.x; py[6] = q.y; px[7] = q.z; py[7] = q.w;
    }

    // Packed keys: squared distance bits (order == norm order for non-negative
    // floats compared as unsigned) with the original index in the 3 LSBs so
    // min() reproduces jnp.argsort's stable tie-break.
    unsigned key[NP];
    #pragma unroll
    for (int k = 0; k < NP; k++) {
        float dx = tx - px[k];
        float dy = ty - py[k];
        float sq = fmaf(dx, dx, dy * dy);
        key[k] = (__float_as_uint(sq) & ~7u) | (unsigned)k;
    }

    // min1/min2 tournament (closest + second-closest). Only the closest
    // (always) and second-closest (ref's default when nothing is valid)
    // depend on sort order; everything else is order-invariant.
    unsigned m1, m2;
    {
        unsigned a1 = umin(key[0], key[1]), a2 = umax(key[0], key[1]);
        unsigned b1 = umin(key[2], key[3]), b2 = umax(key[2], key[3]);
        unsigned c1_ = umin(key[4], key[5]), c2_ = umax(key[4], key[5]);
        unsigned d1 = umin(key[6], key[7]), d2 = umax(key[6], key[7]);
        unsigned e1 = umin(a1, b1);
        unsigned e2 = umin(umax(a1, b1), umin(a2, b2));
        unsigned f1 = umin(c1_, d1);
        unsigned f2 = umin(umax(c1_, d1), umin(c2_, d2));
        m1 = umin(e1, f1);
        m2 = umin(umax(e1, f1), umin(e2, f2));
    }
    int id0 = (int)(m1 & 7u);
    int id1 = (int)(m2 & 7u);

    // Extract closest point via 3-level mux on id0 bits
    float cx, cy;
    {
        bool s0 = (id0 & 1), s1 = (id0 & 2), s2 = (id0 & 4);
        float x01 = s0 ? px[1] : px[0], x23 = s0 ? px[3] : px[2];
        float x45 = s0 ? px[5] : px[4], x67 = s0 ? px[7] : px[6];
        float y01 = s0 ? py[1] : py[0], y23 = s0 ? py[3] : py[2];
        float y45 = s0 ? py[5] : py[4], y67 = s0 ? py[7] : py[6];
        float x03 = s1 ? x23 : x01, x47 = s1 ? x67 : x45;
        float y03 = s1 ? y23 : y01, y47 = s1 ? y67 : y45;
        cx = s2 ? x47 : x03;
        cy = s2 ? y47 : y03;
    }

    // Compact the 7 others in ORIGINAL index order (slot n -> original id
    // n + (n >= id0)), and lift: q_m = (o-c, |o|^2-|c|^2).
    // Reference det(i,j,k) == -[q_i, q_j, q_k] (triple product).
    float sc  = fmaf(cx, cx, cy * cy);
    float v2x = tx - cx, v2y = ty - cy;

    float qx[K], qy[K], qs[K], d00[K], d02[K];
    #pragma unroll
    for (int n = 0; n < K; n++) {
        bool ge = (n >= id0);
        float ox = ge ? px[n + 1] : px[n];
        float oy = ge ? py[n + 1] : py[n];
        qx[n]  = ox - cx;
        qy[n]  = oy - cy;
        qs[n]  = fmaf(ox, ox, oy * oy) - sc;
        d00[n] = fmaf(qx[n], qx[n], qy[n] * qy[n]);
        d02[n] = fmaf(qx[n], v2x, qy[n] * v2y);
    }

    // Precompute all 35 triple products T(a<b<c) = [q_a, q_b, q_c].
    // Each is shared by 3 pairs ((a,b),(a,c),(b,c)) up to permutation sign,
    // replacing 105 in-loop dot products with 35.
    float T[35];
    #pragma unroll
    for (int a = 0; a < K - 1; a++) {
        #pragma unroll
        for (int b = a + 1; b < K - 1; b++) {   // b <= 5: crosses only where some c > b exists
            float crx = fmaf(qy[a], qs[b], -qs[a] * qy[b]);
            float cry = fmaf(qs[a], qx[b], -qx[a] * qs[b]);
            float crz = fmaf(qx[a], qy[b], -qy[a] * qx[b]);
            #pragma unroll
            for (int c = b + 1; c < K; c++) {
                T[tidx(a, b, c)] = fmaf(crx, qx[c], fmaf(cry, qy[c], crz * qs[c]));
            }
        }
    }

    const float INF = __int_as_float(0x7f800000);
    float best = INF;
    float wAs = 0.f, wBs = 0.f;
    int code = 0;

    // Per UNORDERED pair: weights/score identical for both orders
    // (w2(i,j)==w1(j,i)); incircle dets are exact negations, so the shared
    // triples + one min/max pass cover both ordered candidates.
    #pragma unroll
    for (int i = 0; i < K; i++) {
        #pragma unroll
        for (int j = i + 1; j < K; j++) {
            float d01   = fmaf(qx[i], qx[j], qy[i] * qy[j]);
            float denom = fmaf(d00[i], d00[j], -d01 * d01);
            float inv   = __fdividef(1.0f, denom);
            float nA = fmaf(d00[j], d02[i], -d01 * d02[j]);  // -> w2 of (i,j)
            float nB = fmaf(d00[i], d02[j], -d01 * d02[i]);  // -> w1 of (i,j)
            float wA = nA * inv;
            float wB = nB * inv;
            float w0 = 1.0f - wA - wB;
            bool wpos = (w0 > 0.f) && (wA > 0.f) && (wB > 0.f);  // NaN -> false
            // When wpos holds all weights are positive, so max(w^2) == (max w)^2;
            // s is only consumed under (c1|c2) which implies wpos.
            float wmax = fmaxf(w0, fmaxf(wA, wB));
            float s = wmax * wmax;

            // m_k = [q_i,q_j,q_k] gathered from shared triples with
            // permutation sign (one swap = negate, cyclic = same).
            float mn, mx;
            bool first = true;
            #pragma unroll
            for (int k = 0; k < K; k++) {
                if (k == i || k == j) continue;
                float m;
                if (k < i)       m =  T[tidx(k, i, j)];
                else if (k < j)  m = -T[tidx(i, k, j)];
                else             m =  T[tidx(i, j, k)];
                if (first) { mn = m; mx = m; first = false; }
                else       { mn = fminf(mn, m); mx = fmaxf(mx, m); }
            }
            // (i,j) valid <=> det<=0 forall k <=> m_k>=0 forall k
            bool c1 = wpos && (mn >= 0.f);
            bool c2 = wpos && (mx <= 0.f);
            // s is non-NaN whenever (c1|c2); strict < == first-occurrence argmin
            if ((c1 || c2) && (s < best)) {
                best = s;
                wAs  = wA;
                wBs  = wB;
                code = c1 ? ((i << 3) | j) : ((j << 3) | i);
            }
        }
    }

    bool has = best < INF;
    int row = code >> 3, col = code & 7;
    bool fwd = row < col;          // true <=> orientation c1 was selected
    float b0 = 1.0f - wAs - wBs;
    float b1 = fwd ? wAs : wBs;    // w2 of selected ordered pair
    float b2 = fwd ? wBs : wAs;    // w1 of selected ordered pair

    int bn1 = has ? (row + (row >= id0 ? 1 : 0)) : id1;
    int bn2 = has ? (col + (col >= id0 ? 1 : 0)) : id1;

    out[3 * task + 0] = has ? b0 : 0.f;
    out[3 * task + 1] = has ? b1 : 0.f;
    out[3 * task + 2] = has ? b2 : 0.f;

    float* io = out + 3 * NT;
    io[3 * task + 0] = (float)id0;
    io[3 * task + 1] = (float)bn1;
    io[3 * task + 2] = (float)bn2;
}

extern "C" void kernel_launch(void* const* d_in, const int* in_sizes, int n_in,
                              void* d_out, int out_size)
{
    const float* tmpl = (const float*)d_in[0];
    const float* proj = (const float*)d_in[1];
    float* out = (float*)d_out;

    const int threads = 128;
    const int blocks  = (NT + threads - 1) / threads;
    bc_kernel<<<blocks, threads>>>(tmpl, proj, out);
}